// round 1
// baseline (speedup 1.0000x reference)
#include <cuda_runtime.h>
#include <cstdint>
#include <cstddef>

#define NN   100000
#define INF  128
#define HIDF 128
#define OUTF 64

// ---------------- device scratch (static, no allocation) ----------------
__device__ float g_deg[NN];
__device__ float g_dinv[NN];
__device__ float g_h1[(size_t)NN * HIDF];   // x @ W1
__device__ float g_a1[(size_t)NN * HIDF];   // aggregated layer-1 (pre bias/relu)
__device__ float g_h2[(size_t)NN * OUTF];   // relu(a1+b1) @ W2
__device__ float g_a2[(size_t)NN * OUTF];   // aggregated layer-2 (pre bias/sigmoid)
__device__ float g_acc[OUTF];
__device__ int   g_e64;                     // 1 if edge_index is int64, 0 if int32

// ---------------- edge dtype detection ----------------
// If data is int64, every value < 100000 -> high 32 bits zero for ALL entries.
// If data is int32, u64-interpretation pairs two indices -> high word nonzero
// almost surely among 256 samples.
__global__ void k_detect(const unsigned long long* __restrict__ e) {
    int hi = (e[threadIdx.x] >> 32) != 0ULL;
    int any = __syncthreads_or(hi);
    if (threadIdx.x == 0) g_e64 = any ? 0 : 1;
}

__device__ __forceinline__ void load_edge(const void* eidx, long long i, long long E,
                                          int e64, int& s, int& d) {
    if (e64) {
        const long long* p = (const long long*)eidx;
        s = (int)p[i];
        d = (int)p[E + i];
    } else {
        const int* p = (const int*)eidx;
        s = p[i];
        d = p[E + i];
    }
}

// ---------------- degree / norm ----------------
__global__ void k_deg_init() {
    int i = blockIdx.x * blockDim.x + threadIdx.x;
    if (i < NN) g_deg[i] = 1.0f;   // self loop
}

__global__ void k_deg_count(const void* __restrict__ eidx, long long E) {
    long long i = blockIdx.x * (long long)blockDim.x + threadIdx.x;
    if (i >= E) return;
    int e64 = g_e64;
    int d;
    if (e64) d = (int)((const long long*)eidx)[E + i];
    else     d = ((const int*)eidx)[E + i];
    atomicAdd(&g_deg[d], 1.0f);
}

__global__ void k_dinv() {
    int i = blockIdx.x * blockDim.x + threadIdx.x;
    if (i < NN) g_dinv[i] = rsqrtf(g_deg[i]);
}

// ---------------- packed f32x2 helpers (FFMA2 path, 2x fp32 throughput) ----
__device__ __forceinline__ unsigned long long pk2(float lo, float hi) {
    unsigned long long r;
    asm("mov.b64 %0,{%1,%2};" : "=l"(r) : "f"(lo), "f"(hi));
    return r;
}
__device__ __forceinline__ void fma2(unsigned long long& d, unsigned long long a,
                                     unsigned long long b) {
    asm("fma.rn.f32x2 %0,%1,%2,%0;" : "+l"(d) : "l"(a), "l"(b));
}
__device__ __forceinline__ float2 up2(unsigned long long v) {
    float2 r;
    asm("mov.b64 {%0,%1},%2;" : "=f"(r.x), "=f"(r.y) : "l"(v));
    return r;
}

// ---------------- GEMM: C[nrows,BN] = f(A[nrows,128]) @ W[128,BN] ---------
// f = identity when inb==nullptr, else f(v) = relu(v + inb[k]).
template <int BN>
__global__ void __launch_bounds__(256)
k_gemm(const float* __restrict__ A, const float* __restrict__ W,
       const float* __restrict__ inb, float* __restrict__ C, int nrows) {
    const int BM = 128, BK = 16, TN = BN / 16;   // per-thread: 8 rows x TN cols
    __shared__ __align__(16) float As[BK][BM + 4];
    __shared__ __align__(16) float Bs[BK][BN];

    int tid = threadIdx.x;
    int tx = tid & 15;        // col group
    int ty = tid >> 4;        // row group
    int row0 = blockIdx.x * BM;

    unsigned long long acc[8][TN / 2];
#pragma unroll
    for (int i = 0; i < 8; i++)
#pragma unroll
        for (int j = 0; j < TN / 2; j++) acc[i][j] = 0ULL;

    for (int k0 = 0; k0 < 128; k0 += BK) {
        // --- load A tile (transposed into As[k][r]) ---
#pragma unroll
        for (int rep = 0; rep < 2; rep++) {
            int r  = rep * 64 + (tid >> 2);
            int kk = (tid & 3) * 4;
            float4 v = make_float4(0.f, 0.f, 0.f, 0.f);
            if (row0 + r < nrows)
                v = *(const float4*)(A + (size_t)(row0 + r) * 128 + k0 + kk);
            if (inb) {
                float4 bb = *(const float4*)(inb + k0 + kk);
                v.x = fmaxf(v.x + bb.x, 0.f);
                v.y = fmaxf(v.y + bb.y, 0.f);
                v.z = fmaxf(v.z + bb.z, 0.f);
                v.w = fmaxf(v.w + bb.w, 0.f);
            }
            As[kk + 0][r] = v.x;
            As[kk + 1][r] = v.y;
            As[kk + 2][r] = v.z;
            As[kk + 3][r] = v.w;
        }
        // --- load W tile ---
#pragma unroll
        for (int it = 0; it < BN / 64; it++) {
            int idx = it * 256 + tid;
            int k = idx / (BN / 4);
            int c = (idx % (BN / 4)) * 4;
            *(float4*)&Bs[k][c] = *(const float4*)(W + (size_t)(k0 + k) * BN + c);
        }
        __syncthreads();

#pragma unroll
        for (int k = 0; k < BK; k++) {
            float a[8];
            *(float4*)&a[0] = *(const float4*)&As[k][ty * 8];
            *(float4*)&a[4] = *(const float4*)&As[k][ty * 8 + 4];
            unsigned long long bp[TN / 2];
#pragma unroll
            for (int j = 0; j < TN / 2; j++)
                bp[j] = *(const unsigned long long*)&Bs[k][tx * TN + 2 * j];
#pragma unroll
            for (int i = 0; i < 8; i++) {
                unsigned long long ad = pk2(a[i], a[i]);
#pragma unroll
                for (int j = 0; j < TN / 2; j++) fma2(acc[i][j], ad, bp[j]);
            }
        }
        __syncthreads();
    }

#pragma unroll
    for (int i = 0; i < 8; i++) {
        int r = row0 + ty * 8 + i;
        if (r < nrows) {
#pragma unroll
            for (int j = 0; j < TN / 2; j++)
                *(float2*)(C + (size_t)r * BN + tx * TN + 2 * j) = up2(acc[i][j]);
        }
    }
}

// ---------------- aggregation ----------------
// self-loop term: a[i,:] = dinv[i]^2 * h[i,:]
template <int F>
__global__ void k_selfinit(const float* __restrict__ h, float* __restrict__ a) {
    long long i = blockIdx.x * (long long)blockDim.x + threadIdx.x;
    long long tot = (long long)NN * (F / 4);
    if (i >= tot) return;
    int node = (int)(i / (F / 4));
    float s = g_dinv[node];
    s *= s;
    float4 v = ((const float4*)h)[i];
    v.x *= s; v.y *= s; v.z *= s; v.w *= s;
    ((float4*)a)[i] = v;
}

// edge term: a[dst,:] += h[src,:] * dinv[src]*dinv[dst]   (vector RED, no return)
template <int F>
__global__ void k_agg(const void* __restrict__ eidx, long long E,
                      const float* __restrict__ h, float* __restrict__ a) {
    const int LPE = F / 4;   // threads per edge (float4 per thread)
    long long gid = blockIdx.x * (long long)blockDim.x + threadIdx.x;
    long long e = gid / LPE;
    int lane = (int)(gid % LPE);
    if (e >= E) return;
    int e64 = g_e64;
    int s, d;
    load_edge(eidx, e, E, e64, s, d);
    float nrm = g_dinv[s] * g_dinv[d];
    float4 v = *(const float4*)(h + (size_t)s * F + lane * 4);
    float* o = a + (size_t)d * F + lane * 4;
    asm volatile("red.global.add.v4.f32 [%0], {%1,%2,%3,%4};"
                 :: "l"(o), "f"(v.x * nrm), "f"(v.y * nrm),
                    "f"(v.z * nrm), "f"(v.w * nrm)
                 : "memory");
}

// ---------------- final reduce: mean over nodes of sigmoid(a2 + b2) -------
__global__ void k_acc_zero() {
    if (threadIdx.x < OUTF) g_acc[threadIdx.x] = 0.f;
}

__global__ void k_reduce(const float* __restrict__ a2, const float* __restrict__ b2) {
    __shared__ float sm[256];
    int col = threadIdx.x & 63;
    int grp = threadIdx.x >> 6;   // 0..3
    float bb = b2[col];
    float p = 0.f;
    for (int node = blockIdx.x * 4 + grp; node < NN; node += gridDim.x * 4) {
        float v = a2[(size_t)node * OUTF + col] + bb;
        p += 1.0f / (1.0f + expf(-v));
    }
    sm[threadIdx.x] = p;
    __syncthreads();
    if (threadIdx.x < 64)
        atomicAdd(&g_acc[col], sm[col] + sm[col + 64] + sm[col + 128] + sm[col + 192]);
}

__global__ void k_final(float* __restrict__ out) {
    if (threadIdx.x < OUTF) out[threadIdx.x] = g_acc[threadIdx.x] * (1.0f / NN);
}

// ---------------- launch ----------------
extern "C" void kernel_launch(void* const* d_in, const int* in_sizes, int n_in,
                              void* d_out, int out_size) {
    const float* x  = (const float*)d_in[0];
    const void*  ei = d_in[1];
    const float* W1 = (const float*)d_in[2];
    const float* b1 = (const float*)d_in[3];
    const float* W2 = (const float*)d_in[4];
    const float* b2 = (const float*)d_in[5];
    float* out = (float*)d_out;
    long long E = in_sizes[1] / 2;

    float *h1, *a1, *h2, *a2;
    cudaGetSymbolAddress((void**)&h1, g_h1);
    cudaGetSymbolAddress((void**)&a1, g_a1);
    cudaGetSymbolAddress((void**)&h2, g_h2);
    cudaGetSymbolAddress((void**)&a2, g_a2);

    int nb = (NN + 255) / 256;
    int gb = (NN + 127) / 128;

    k_detect<<<1, 256>>>((const unsigned long long*)ei);
    k_deg_init<<<nb, 256>>>();
    k_deg_count<<<(int)((E + 255) / 256), 256>>>(ei, E);
    k_dinv<<<nb, 256>>>();

    // Layer 1
    k_gemm<128><<<gb, 256>>>(x, W1, nullptr, h1, NN);
    k_selfinit<128><<<(int)(((long long)NN * 32 + 255) / 256), 256>>>(h1, a1);
    k_agg<128><<<(int)((E * 32 + 255) / 256), 256>>>(ei, E, h1, a1);

    // Layer 2 (bias+relu of layer 1 fused into GEMM2's A-load)
    k_gemm<64><<<gb, 256>>>(a1, W2, b1, h2, NN);
    k_selfinit<64><<<(int)(((long long)NN * 16 + 255) / 256), 256>>>(h2, a2);
    k_agg<64><<<(int)((E * 16 + 255) / 256), 256>>>(ei, E, h2, a2);

    // Output
    k_acc_zero<<<1, 64>>>();
    k_reduce<<<512, 256>>>(a2, b2);
    k_final<<<1, 64>>>(out);
}

// round 2
// speedup vs baseline: 1.8217x; 1.8217x over previous
#include <cuda_runtime.h>
#include <cuda_bf16.h>
#include <cstdint>
#include <cstddef>

#define NN   100000
#define MAXE 1600000
#define NB   391          // ceil(NN/256)

// ---------------- device scratch ----------------
__device__ int   g_degi[NN];
__device__ float g_dinv[NN];
__device__ int   g_rowptr[NN + 1];
__device__ int   g_cursor[NN];
__device__ int   g_bsum[NB];
__device__ int   g_boff[NB];
__device__ int   g_csrc[MAXE];
__device__ float g_cnorm[MAXE];
__device__ __nv_bfloat16 g_h1[(size_t)NN * 128];
__device__ float         g_a1[(size_t)NN * 128];
__device__ __nv_bfloat16 g_h2[(size_t)NN * 64];
__device__ float         g_a2[(size_t)NN * 64];
__device__ float g_acc[64];
__device__ int   g_e64;

// ---------------- edge dtype detection ----------------
__global__ void k_detect(const unsigned long long* __restrict__ e) {
    int hi = (e[threadIdx.x] >> 32) != 0ULL;
    int any = __syncthreads_or(hi);
    if (threadIdx.x == 0) g_e64 = any ? 0 : 1;
}

__device__ __forceinline__ void load_edge(const void* eidx, long long i, long long E,
                                          int e64, int& s, int& d) {
    if (e64) {
        const long long* p = (const long long*)eidx;
        s = (int)p[i];
        d = (int)p[E + i];
    } else {
        const int* p = (const int*)eidx;
        s = p[i];
        d = p[E + i];
    }
}

// ---------------- degree / norm ----------------
__global__ void k_zero_deg() {
    int i = blockIdx.x * blockDim.x + threadIdx.x;
    if (i < NN) g_degi[i] = 0;
}

__global__ void k_degcount(const void* __restrict__ eidx, long long E) {
    long long i = blockIdx.x * (long long)blockDim.x + threadIdx.x;
    if (i >= E) return;
    int d;
    if (g_e64) d = (int)((const long long*)eidx)[E + i];
    else       d = ((const int*)eidx)[E + i];
    atomicAdd(&g_degi[d], 1);
}

__global__ void k_dinv() {
    int i = blockIdx.x * blockDim.x + threadIdx.x;
    if (i < NN) g_dinv[i] = rsqrtf((float)(g_degi[i] + 1));  // +1 self loop
}

// ---------------- prefix scan (3 kernels) ----------------
__global__ void k_scan1() {
    __shared__ int sm[256];
    int i = blockIdx.x * 256 + threadIdx.x;
    sm[threadIdx.x] = (i < NN) ? g_degi[i] : 0;
    __syncthreads();
    for (int o = 128; o > 0; o >>= 1) {
        if (threadIdx.x < o) sm[threadIdx.x] += sm[threadIdx.x + o];
        __syncthreads();
    }
    if (threadIdx.x == 0) g_bsum[blockIdx.x] = sm[0];
}

__global__ void k_scan2() {
    __shared__ int sm[512];
    int v = (threadIdx.x < NB) ? g_bsum[threadIdx.x] : 0;
    sm[threadIdx.x] = v;
    __syncthreads();
    for (int o = 1; o < 512; o <<= 1) {
        int t = (threadIdx.x >= o) ? sm[threadIdx.x - o] : 0;
        __syncthreads();
        sm[threadIdx.x] += t;
        __syncthreads();
    }
    if (threadIdx.x < NB) g_boff[threadIdx.x] = sm[threadIdx.x] - v;  // exclusive
}

__global__ void k_scan3() {
    __shared__ int sm[256];
    int i = blockIdx.x * 256 + threadIdx.x;
    int v = (i < NN) ? g_degi[i] : 0;
    sm[threadIdx.x] = v;
    __syncthreads();
    for (int o = 1; o < 256; o <<= 1) {
        int t = (threadIdx.x >= o) ? sm[threadIdx.x - o] : 0;
        __syncthreads();
        sm[threadIdx.x] += t;
        __syncthreads();
    }
    int excl = sm[threadIdx.x] - v + g_boff[blockIdx.x];
    if (i < NN) { g_rowptr[i] = excl; g_cursor[i] = excl; }
    if (i == NN - 1) g_rowptr[NN] = excl + v;
}

__global__ void k_scatter(const void* __restrict__ eidx, long long E) {
    long long i = blockIdx.x * (long long)blockDim.x + threadIdx.x;
    if (i >= E) return;
    int e64 = g_e64;
    int s, d;
    load_edge(eidx, i, E, e64, s, d);
    int pos = atomicAdd(&g_cursor[d], 1);
    g_csrc[pos]  = s;
    g_cnorm[pos] = g_dinv[s] * g_dinv[d];
}

// ---------------- packed f32x2 helpers ----------------
__device__ __forceinline__ unsigned long long pk2(float lo, float hi) {
    unsigned long long r;
    asm("mov.b64 %0,{%1,%2};" : "=l"(r) : "f"(lo), "f"(hi));
    return r;
}
__device__ __forceinline__ void fma2(unsigned long long& d, unsigned long long a,
                                     unsigned long long b) {
    asm("fma.rn.f32x2 %0,%1,%2,%0;" : "+l"(d) : "l"(a), "l"(b));
}
__device__ __forceinline__ float2 up2(unsigned long long v) {
    float2 r;
    asm("mov.b64 {%0,%1},%2;" : "=f"(r.x), "=f"(r.y) : "l"(v));
    return r;
}

// ---------------- GEMM: C[nrows,BN](bf16) = f(A[nrows,128]) @ W[128,BN] ----
// f = identity when inb==nullptr, else f(v) = relu(v + inb[k]).
template <int BN>
__global__ void __launch_bounds__(256)
k_gemm(const float* __restrict__ A, const float* __restrict__ W,
       const float* __restrict__ inb, __nv_bfloat16* __restrict__ C, int nrows) {
    const int BM = 128, BK = 16, TN = BN / 16;
    __shared__ __align__(16) float As[BK][BM + 4];
    __shared__ __align__(16) float Bs[BK][BN];

    int tid = threadIdx.x;
    int tx = tid & 15;
    int ty = tid >> 4;
    int row0 = blockIdx.x * BM;

    unsigned long long acc[8][TN / 2];
#pragma unroll
    for (int i = 0; i < 8; i++)
#pragma unroll
        for (int j = 0; j < TN / 2; j++) acc[i][j] = 0ULL;

    for (int k0 = 0; k0 < 128; k0 += BK) {
#pragma unroll
        for (int rep = 0; rep < 2; rep++) {
            int r  = rep * 64 + (tid >> 2);
            int kk = (tid & 3) * 4;
            float4 v = make_float4(0.f, 0.f, 0.f, 0.f);
            if (row0 + r < nrows)
                v = *(const float4*)(A + (size_t)(row0 + r) * 128 + k0 + kk);
            if (inb) {
                float4 bb = *(const float4*)(inb + k0 + kk);
                v.x = fmaxf(v.x + bb.x, 0.f);
                v.y = fmaxf(v.y + bb.y, 0.f);
                v.z = fmaxf(v.z + bb.z, 0.f);
                v.w = fmaxf(v.w + bb.w, 0.f);
            }
            As[kk + 0][r] = v.x;
            As[kk + 1][r] = v.y;
            As[kk + 2][r] = v.z;
            As[kk + 3][r] = v.w;
        }
#pragma unroll
        for (int it = 0; it < BN / 64; it++) {
            int idx = it * 256 + tid;
            int k = idx / (BN / 4);
            int c = (idx % (BN / 4)) * 4;
            *(float4*)&Bs[k][c] = *(const float4*)(W + (size_t)(k0 + k) * BN + c);
        }
        __syncthreads();

#pragma unroll
        for (int k = 0; k < BK; k++) {
            float a[8];
            *(float4*)&a[0] = *(const float4*)&As[k][ty * 8];
            *(float4*)&a[4] = *(const float4*)&As[k][ty * 8 + 4];
            unsigned long long bp[TN / 2];
#pragma unroll
            for (int j = 0; j < TN / 2; j++)
                bp[j] = *(const unsigned long long*)&Bs[k][tx * TN + 2 * j];
#pragma unroll
            for (int i = 0; i < 8; i++) {
                unsigned long long ad = pk2(a[i], a[i]);
#pragma unroll
                for (int j = 0; j < TN / 2; j++) fma2(acc[i][j], ad, bp[j]);
            }
        }
        __syncthreads();
    }

#pragma unroll
    for (int i = 0; i < 8; i++) {
        int r = row0 + ty * 8 + i;
        if (r < nrows) {
#pragma unroll
            for (int j = 0; j < TN / 2; j++) {
                float2 v = up2(acc[i][j]);
                __nv_bfloat162 bv = __float22bfloat162_rn(v);
                *(__nv_bfloat162*)(C + (size_t)r * BN + tx * TN + 2 * j) = bv;
            }
        }
    }
}

// ---------------- CSR aggregation: one warp per dst node ------------------
// a[node,:] = dinv[node]^2 * h[node,:] + sum_e cnorm[e] * h[csrc[e],:]
template <int F>
__device__ __forceinline__ void ldrow(const __nv_bfloat16* p, float* f) {
    if (F == 128) {
        uint2 u = *(const uint2*)p;
        float2 a = __bfloat1622float2(*(__nv_bfloat162*)&u.x);
        float2 b = __bfloat1622float2(*(__nv_bfloat162*)&u.y);
        f[0] = a.x; f[1] = a.y; f[2] = b.x; f[3] = b.y;
    } else {
        __nv_bfloat162 u = *(const __nv_bfloat162*)p;
        float2 a = __bfloat1622float2(u);
        f[0] = a.x; f[1] = a.y;
    }
}

template <int F>
__global__ void __launch_bounds__(256)
k_agg_csr(const __nv_bfloat16* __restrict__ h, float* __restrict__ a) {
    const int C = F / 32;                     // floats per lane
    int node = (blockIdx.x * 256 + threadIdx.x) >> 5;
    int lane = threadIdx.x & 31;
    if (node >= NN) return;

    const __nv_bfloat16* hl = h + lane * C;
    float acc[C];

    // self-loop term
    {
        float sd = g_dinv[node];
        sd *= sd;
        float f[C];
        ldrow<F>(hl + (size_t)node * F, f);
#pragma unroll
        for (int c = 0; c < C; c++) acc[c] = sd * f[c];
    }

    int beg = g_rowptr[node], end = g_rowptr[node + 1];
    int j = beg;
    for (; j + 4 <= end; j += 4) {
        int   s0 = g_csrc[j],     s1 = g_csrc[j + 1];
        int   s2 = g_csrc[j + 2], s3 = g_csrc[j + 3];
        float n0 = g_cnorm[j],     n1 = g_cnorm[j + 1];
        float n2 = g_cnorm[j + 2], n3 = g_cnorm[j + 3];
        float f0[C], f1[C], f2[C], f3[C];
        ldrow<F>(hl + (size_t)s0 * F, f0);
        ldrow<F>(hl + (size_t)s1 * F, f1);
        ldrow<F>(hl + (size_t)s2 * F, f2);
        ldrow<F>(hl + (size_t)s3 * F, f3);
#pragma unroll
        for (int c = 0; c < C; c++)
            acc[c] += n0 * f0[c] + n1 * f1[c] + n2 * f2[c] + n3 * f3[c];
    }
    for (; j < end; j++) {
        int s = g_csrc[j];
        float n = g_cnorm[j];
        float f[C];
        ldrow<F>(hl + (size_t)s * F, f);
#pragma unroll
        for (int c = 0; c < C; c++) acc[c] += n * f[c];
    }

    float* o = a + (size_t)node * F + lane * C;
    if (F == 128) *(float4*)o = make_float4(acc[0], acc[1], acc[2], acc[3]);
    else          *(float2*)o = make_float2(acc[0], acc[1]);
}

// ---------------- final reduce ----------------
__global__ void k_acc_zero() {
    if (threadIdx.x < 64) g_acc[threadIdx.x] = 0.f;
}

__global__ void k_reduce(const float* __restrict__ a2, const float* __restrict__ b2) {
    __shared__ float sm[256];
    int col = threadIdx.x & 63;
    int grp = threadIdx.x >> 6;
    float bb = b2[col];
    float p = 0.f;
    for (int node = blockIdx.x * 4 + grp; node < NN; node += gridDim.x * 4) {
        float v = a2[(size_t)node * 64 + col] + bb;
        p += 1.0f / (1.0f + expf(-v));
    }
    sm[threadIdx.x] = p;
    __syncthreads();
    if (threadIdx.x < 64)
        atomicAdd(&g_acc[col], sm[col] + sm[col + 64] + sm[col + 128] + sm[col + 192]);
}

__global__ void k_final(float* __restrict__ out) {
    if (threadIdx.x < 64) out[threadIdx.x] = g_acc[threadIdx.x] * (1.0f / NN);
}

// ---------------- launch ----------------
extern "C" void kernel_launch(void* const* d_in, const int* in_sizes, int n_in,
                              void* d_out, int out_size) {
    const float* x  = (const float*)d_in[0];
    const void*  ei = d_in[1];
    const float* W1 = (const float*)d_in[2];
    const float* b1 = (const float*)d_in[3];
    const float* W2 = (const float*)d_in[4];
    const float* b2 = (const float*)d_in[5];
    float* out = (float*)d_out;
    long long E = in_sizes[1] / 2;

    __nv_bfloat16 *h1, *h2;
    float *a1, *a2;
    cudaGetSymbolAddress((void**)&h1, g_h1);
    cudaGetSymbolAddress((void**)&a1, g_a1);
    cudaGetSymbolAddress((void**)&h2, g_h2);
    cudaGetSymbolAddress((void**)&a2, g_a2);

    int eb = (int)((E + 255) / 256);
    int gb = (NN + 127) / 128;
    int wb = (NN * 32 + 255) / 256;   // one warp per node

    k_detect<<<1, 256>>>((const unsigned long long*)ei);
    k_zero_deg<<<NB, 256>>>();
    k_degcount<<<eb, 256>>>(ei, E);
    k_dinv<<<NB, 256>>>();
    k_scan1<<<NB, 256>>>();
    k_scan2<<<1, 512>>>();
    k_scan3<<<NB, 256>>>();
    k_scatter<<<eb, 256>>>(ei, E);

    // Layer 1
    k_gemm<128><<<gb, 256>>>(x, W1, nullptr, h1, NN);
    k_agg_csr<128><<<wb, 256>>>(h1, a1);

    // Layer 2 (bias+relu fused into GEMM2's A-load)
    k_gemm<64><<<gb, 256>>>(a1, W2, b1, h2, NN);
    k_agg_csr<64><<<wb, 256>>>(h2, a2);

    // Output
    k_acc_zero<<<1, 64>>>();
    k_reduce<<<512, 256>>>(a2, b2);
    k_final<<<1, 64>>>(out);
}

// round 3
// speedup vs baseline: 2.3038x; 1.2646x over previous
#include <cuda_runtime.h>
#include <cuda_bf16.h>
#include <cstdint>
#include <cstddef>

#define NN   100000
#define MAXE 1600000
#define NB   391          // ceil(NN/256)

// ---------------- device scratch ----------------
__device__ int   g_degi[NN];
__device__ float g_dinv[NN];
__device__ int   g_rowptr[NN + 1];
__device__ int   g_cursor[NN];
__device__ int   g_bsum[NB];
__device__ int   g_boff[NB];
__device__ int   g_csrc[MAXE];
__device__ float g_cnorm[MAXE];
__device__ __nv_bfloat16 g_h1[(size_t)NN * 128];  // x @ W1            (bf16)
__device__ __nv_bfloat16 g_t1[(size_t)NN * 128];  // relu(agg1 + b1)   (bf16)
__device__ __nv_bfloat16 g_h2[(size_t)NN * 64];   // t1 @ W2           (bf16)
__device__ float g_acc[64];
__device__ int   g_e64;

// ---------------- edge dtype detection ----------------
__global__ void k_detect(const unsigned long long* __restrict__ e) {
    int hi = (e[threadIdx.x] >> 32) != 0ULL;
    int any = __syncthreads_or(hi);
    if (threadIdx.x == 0) g_e64 = any ? 0 : 1;
}

__device__ __forceinline__ void load_edge(const void* eidx, long long i, long long E,
                                          int e64, int& s, int& d) {
    if (e64) {
        const long long* p = (const long long*)eidx;
        s = (int)p[i];
        d = (int)p[E + i];
    } else {
        const int* p = (const int*)eidx;
        s = p[i];
        d = p[E + i];
    }
}

// ---------------- degree / norm ----------------
__global__ void k_zero_deg() {
    int i = blockIdx.x * blockDim.x + threadIdx.x;
    if (i < NN) g_degi[i] = 0;
}

__global__ void k_degcount(const void* __restrict__ eidx, long long E) {
    long long i = blockIdx.x * (long long)blockDim.x + threadIdx.x;
    if (i >= E) return;
    int d;
    if (g_e64) d = (int)((const long long*)eidx)[E + i];
    else       d = ((const int*)eidx)[E + i];
    atomicAdd(&g_degi[d], 1);
}

__global__ void k_dinv() {
    int i = blockIdx.x * blockDim.x + threadIdx.x;
    if (i < NN) g_dinv[i] = rsqrtf((float)(g_degi[i] + 1));  // +1 self loop
}

// ---------------- prefix scan (3 kernels) ----------------
__global__ void k_scan1() {
    __shared__ int sm[256];
    int i = blockIdx.x * 256 + threadIdx.x;
    sm[threadIdx.x] = (i < NN) ? g_degi[i] : 0;
    __syncthreads();
    for (int o = 128; o > 0; o >>= 1) {
        if (threadIdx.x < o) sm[threadIdx.x] += sm[threadIdx.x + o];
        __syncthreads();
    }
    if (threadIdx.x == 0) g_bsum[blockIdx.x] = sm[0];
}

__global__ void k_scan2() {
    __shared__ int sm[512];
    int v = (threadIdx.x < NB) ? g_bsum[threadIdx.x] : 0;
    sm[threadIdx.x] = v;
    __syncthreads();
    for (int o = 1; o < 512; o <<= 1) {
        int t = (threadIdx.x >= o) ? sm[threadIdx.x - o] : 0;
        __syncthreads();
        sm[threadIdx.x] += t;
        __syncthreads();
    }
    if (threadIdx.x < NB) g_boff[threadIdx.x] = sm[threadIdx.x] - v;  // exclusive
}

__global__ void k_scan3() {
    __shared__ int sm[256];
    int i = blockIdx.x * 256 + threadIdx.x;
    int v = (i < NN) ? g_degi[i] : 0;
    sm[threadIdx.x] = v;
    __syncthreads();
    for (int o = 1; o < 256; o <<= 1) {
        int t = (threadIdx.x >= o) ? sm[threadIdx.x - o] : 0;
        __syncthreads();
        sm[threadIdx.x] += t;
        __syncthreads();
    }
    int excl = sm[threadIdx.x] - v + g_boff[blockIdx.x];
    if (i < NN) { g_rowptr[i] = excl; g_cursor[i] = excl; }
    if (i == NN - 1) g_rowptr[NN] = excl + v;
}

__global__ void k_scatter(const void* __restrict__ eidx, long long E) {
    long long i = blockIdx.x * (long long)blockDim.x + threadIdx.x;
    if (i >= E) return;
    int e64 = g_e64;
    int s, d;
    load_edge(eidx, i, E, e64, s, d);
    int pos = atomicAdd(&g_cursor[d], 1);
    g_csrc[pos]  = s;
    g_cnorm[pos] = g_dinv[s] * g_dinv[d];
}

// ---------------- tensor-core GEMM ----------------
__device__ __forceinline__ uint32_t smem_u32(const void* p) {
    return (uint32_t)__cvta_generic_to_shared(p);
}
__device__ __forceinline__ void ldsm4(uint32_t* r, uint32_t addr) {
    asm volatile("ldmatrix.sync.aligned.m8n8.x4.shared.b16 {%0,%1,%2,%3},[%4];"
                 : "=r"(r[0]), "=r"(r[1]), "=r"(r[2]), "=r"(r[3]) : "r"(addr));
}
__device__ __forceinline__ void ldsm4t(uint32_t* r, uint32_t addr) {
    asm volatile("ldmatrix.sync.aligned.m8n8.x4.trans.shared.b16 {%0,%1,%2,%3},[%4];"
                 : "=r"(r[0]), "=r"(r[1]), "=r"(r[2]), "=r"(r[3]) : "r"(addr));
}
__device__ __forceinline__ void mma16816(float* d, const uint32_t* a, const uint32_t* b) {
    asm volatile(
        "mma.sync.aligned.m16n8k16.row.col.f32.bf16.bf16.f32 "
        "{%0,%1,%2,%3},{%4,%5,%6,%7},{%8,%9},{%0,%1,%2,%3};"
        : "+f"(d[0]), "+f"(d[1]), "+f"(d[2]), "+f"(d[3])
        : "r"(a[0]), "r"(a[1]), "r"(a[2]), "r"(a[3]), "r"(b[0]), "r"(b[1]));
}

// C[nrows,BN](bf16) = A[nrows,128] @ W[128,BN].  A fp32 or bf16 per A_BF16.
// BM=128, full K=128 in one smem tile. 256 threads = 8 warps (4m x 2n).
template <int BN, bool A_BF16>
__global__ void __launch_bounds__(256)
k_gemm_tc(const void* __restrict__ Av, const float* __restrict__ W,
          __nv_bfloat16* __restrict__ C, int nrows) {
    const int LDA = 136;          // bf16 elems per As row (+16B pad)
    const int LDB = BN + 8;
    extern __shared__ __nv_bfloat16 smem[];
    __nv_bfloat16* As = smem;                       // [128][LDA]
    __nv_bfloat16* Bs = smem + 128 * LDA;           // [128][LDB]

    int tid  = threadIdx.x;
    int lane = tid & 31;
    int w    = tid >> 5;
    int wm   = w & 3;             // m group (32 rows)
    int wn   = w >> 2;            // n group (BN/2 cols)
    int row0 = blockIdx.x * 128;

    // ---- load A tile ----
    if (A_BF16) {
        const __nv_bfloat16* A = (const __nv_bfloat16*)Av;
        for (int idx = tid; idx < 128 * 16; idx += 256) {
            int r = idx >> 4, c8 = (idx & 15) * 8;
            uint4 v = make_uint4(0, 0, 0, 0);
            if (row0 + r < nrows)
                v = *(const uint4*)(A + (size_t)(row0 + r) * 128 + c8);
            *(uint4*)&As[r * LDA + c8] = v;
        }
    } else {
        const float* A = (const float*)Av;
        for (int idx = tid; idx < 128 * 32; idx += 256) {
            int r = idx >> 5, c4 = (idx & 31) * 4;
            float4 v = make_float4(0.f, 0.f, 0.f, 0.f);
            if (row0 + r < nrows)
                v = *(const float4*)(A + (size_t)(row0 + r) * 128 + c4);
            __nv_bfloat162 lo = __float22bfloat162_rn(make_float2(v.x, v.y));
            __nv_bfloat162 hi = __float22bfloat162_rn(make_float2(v.z, v.w));
            uint2 pk;
            pk.x = *(uint32_t*)&lo;
            pk.y = *(uint32_t*)&hi;
            *(uint2*)&As[r * LDA + c4] = pk;
        }
    }
    // ---- load W tile (fp32 -> bf16) ----
    for (int idx = tid; idx < 128 * (BN / 4); idx += 256) {
        int r = idx / (BN / 4), c4 = (idx % (BN / 4)) * 4;
        float4 v = *(const float4*)(W + (size_t)r * BN + c4);
        __nv_bfloat162 lo = __float22bfloat162_rn(make_float2(v.x, v.y));
        __nv_bfloat162 hi = __float22bfloat162_rn(make_float2(v.z, v.w));
        uint2 pk;
        pk.x = *(uint32_t*)&lo;
        pk.y = *(uint32_t*)&hi;
        *(uint2*)&Bs[r * LDB + c4] = pk;
    }
    __syncthreads();

    const int NF8 = BN / 16;      // n8 frags per warp
    const int NT  = NF8 / 2;      // ldmatrix.x4.trans per k-step (n16 each)
    float acc[2][NF8][4];
#pragma unroll
    for (int i = 0; i < 2; i++)
#pragma unroll
        for (int j = 0; j < NF8; j++)
#pragma unroll
            for (int q = 0; q < 4; q++) acc[i][j][q] = 0.f;

    int rsel = lane & 15;
    int csel = (lane >> 4) * 8;
    int mw0  = wm * 32;
    int nw0  = wn * (BN / 2);

#pragma unroll
    for (int ks = 0; ks < 8; ks++) {
        int k0 = ks * 16;
        uint32_t af[2][4];
#pragma unroll
        for (int mi = 0; mi < 2; mi++)
            ldsm4(af[mi], smem_u32(&As[(mw0 + mi * 16 + rsel) * LDA + k0 + csel]));
        uint32_t bf[NT][4];
#pragma unroll
        for (int nt = 0; nt < NT; nt++)
            ldsm4t(bf[nt], smem_u32(&Bs[(k0 + rsel) * LDB + nw0 + nt * 16 + csel]));
#pragma unroll
        for (int mi = 0; mi < 2; mi++)
#pragma unroll
            for (int nj = 0; nj < NF8; nj++)
                mma16816(acc[mi][nj], af[mi], &bf[nj >> 1][(nj & 1) * 2]);
    }

    // ---- epilogue: bf16 store ----
    int g = lane >> 2, q = lane & 3;
#pragma unroll
    for (int mi = 0; mi < 2; mi++) {
        int r0 = row0 + mw0 + mi * 16 + g;
#pragma unroll
        for (int nj = 0; nj < NF8; nj++) {
            int col = nw0 + nj * 8 + q * 2;
            if (r0 < nrows) {
                __nv_bfloat162 v = __float22bfloat162_rn(
                    make_float2(acc[mi][nj][0], acc[mi][nj][1]));
                *(__nv_bfloat162*)(C + (size_t)r0 * BN + col) = v;
            }
            if (r0 + 8 < nrows) {
                __nv_bfloat162 v = __float22bfloat162_rn(
                    make_float2(acc[mi][nj][2], acc[mi][nj][3]));
                *(__nv_bfloat162*)(C + (size_t)(r0 + 8) * BN + col) = v;
            }
        }
    }
}

// ---------------- CSR aggregation helpers ----------------
template <int F>
__device__ __forceinline__ void ldrow(const __nv_bfloat16* p, float* f) {
    if (F == 128) {
        uint2 u = *(const uint2*)p;
        float2 a = __bfloat1622float2(*(__nv_bfloat162*)&u.x);
        float2 b = __bfloat1622float2(*(__nv_bfloat162*)&u.y);
        f[0] = a.x; f[1] = a.y; f[2] = b.x; f[3] = b.y;
    } else {
        __nv_bfloat162 u = *(const __nv_bfloat162*)p;
        float2 a = __bfloat1622float2(u);
        f[0] = a.x; f[1] = a.y;
    }
}

template <int F, int C>
__device__ __forceinline__ void csr_accum(const __nv_bfloat16* hl, int node, float* acc) {
    // self-loop term
    {
        float sd = g_dinv[node];
        sd *= sd;
        float f[C];
        ldrow<F>(hl + (size_t)node * F, f);
#pragma unroll
        for (int c = 0; c < C; c++) acc[c] = sd * f[c];
    }
    int beg = g_rowptr[node], end = g_rowptr[node + 1];
    int j = beg;
    for (; j + 4 <= end; j += 4) {
        int   s0 = g_csrc[j],     s1 = g_csrc[j + 1];
        int   s2 = g_csrc[j + 2], s3 = g_csrc[j + 3];
        float n0 = g_cnorm[j],     n1 = g_cnorm[j + 1];
        float n2 = g_cnorm[j + 2], n3 = g_cnorm[j + 3];
        float f0[C], f1[C], f2[C], f3[C];
        ldrow<F>(hl + (size_t)s0 * F, f0);
        ldrow<F>(hl + (size_t)s1 * F, f1);
        ldrow<F>(hl + (size_t)s2 * F, f2);
        ldrow<F>(hl + (size_t)s3 * F, f3);
#pragma unroll
        for (int c = 0; c < C; c++)
            acc[c] += n0 * f0[c] + n1 * f1[c] + n2 * f2[c] + n3 * f3[c];
    }
    for (; j < end; j++) {
        int s = g_csrc[j];
        float n = g_cnorm[j];
        float f[C];
        ldrow<F>(hl + (size_t)s * F, f);
#pragma unroll
        for (int c = 0; c < C; c++) acc[c] += n * f[c];
    }
}

// agg layer 1: t1[node,:] = bf16(relu(agg(h1)[node,:] + b1))
__global__ void __launch_bounds__(256)
k_agg1(const __nv_bfloat16* __restrict__ h, const float* __restrict__ b1,
       __nv_bfloat16* __restrict__ t1) {
    int node = (blockIdx.x * 256 + threadIdx.x) >> 5;
    int lane = threadIdx.x & 31;
    if (node >= NN) return;
    float acc[4];
    csr_accum<128, 4>(h + lane * 4, node, acc);
    float4 bb = *(const float4*)(b1 + lane * 4);
    float2 lo = make_float2(fmaxf(acc[0] + bb.x, 0.f), fmaxf(acc[1] + bb.y, 0.f));
    float2 hi = make_float2(fmaxf(acc[2] + bb.z, 0.f), fmaxf(acc[3] + bb.w, 0.f));
    uint2 pk;
    __nv_bfloat162 l2 = __float22bfloat162_rn(lo);
    __nv_bfloat162 h2 = __float22bfloat162_rn(hi);
    pk.x = *(uint32_t*)&l2;
    pk.y = *(uint32_t*)&h2;
    *(uint2*)(t1 + (size_t)node * 128 + lane * 4) = pk;
}

// agg layer 2 fused with sigmoid + mean: g_acc[c] += sum_nodes sigmoid(agg+b2)
__global__ void __launch_bounds__(256)
k_agg2(const __nv_bfloat16* __restrict__ h, const float* __restrict__ b2) {
    __shared__ float sm[64];
    if (threadIdx.x < 64) sm[threadIdx.x] = 0.f;
    __syncthreads();

    int warp = threadIdx.x >> 5;
    int lane = threadIdx.x & 31;
    float2 bb = *(const float2*)(b2 + lane * 2);
    float s0 = 0.f, s1 = 0.f;

    for (int node = blockIdx.x * 8 + warp; node < NN; node += gridDim.x * 8) {
        float acc[2];
        csr_accum<64, 2>(h + lane * 2, node, acc);
        float v0 = acc[0] + bb.x;
        float v1 = acc[1] + bb.y;
        s0 += 1.0f / (1.0f + __expf(-v0));
        s1 += 1.0f / (1.0f + __expf(-v1));
    }
    atomicAdd(&sm[lane * 2], s0);
    atomicAdd(&sm[lane * 2 + 1], s1);
    __syncthreads();
    if (threadIdx.x < 64) atomicAdd(&g_acc[threadIdx.x], sm[threadIdx.x]);
}

__global__ void k_acc_zero() {
    if (threadIdx.x < 64) g_acc[threadIdx.x] = 0.f;
}

__global__ void k_final(float* __restrict__ out) {
    if (threadIdx.x < 64) out[threadIdx.x] = g_acc[threadIdx.x] * (1.0f / NN);
}

// ---------------- launch ----------------
extern "C" void kernel_launch(void* const* d_in, const int* in_sizes, int n_in,
                              void* d_out, int out_size) {
    const float* x  = (const float*)d_in[0];
    const void*  ei = d_in[1];
    const float* W1 = (const float*)d_in[2];
    const float* b1 = (const float*)d_in[3];
    const float* W2 = (const float*)d_in[4];
    const float* b2 = (const float*)d_in[5];
    float* out = (float*)d_out;
    long long E = in_sizes[1] / 2;

    __nv_bfloat16 *h1, *t1, *h2;
    cudaGetSymbolAddress((void**)&h1, g_h1);
    cudaGetSymbolAddress((void**)&t1, g_t1);
    cudaGetSymbolAddress((void**)&h2, g_h2);

    const int SM1 = (128 * 136 + 128 * 136) * 2;  // 69632 B
    const int SM2 = (128 * 136 + 128 * 72) * 2;   // 53248 B
    static int attr_done = 0;
    if (!attr_done) {
        cudaFuncSetAttribute(k_gemm_tc<128, false>,
                             cudaFuncAttributeMaxDynamicSharedMemorySize, SM1);
        cudaFuncSetAttribute(k_gemm_tc<64, true>,
                             cudaFuncAttributeMaxDynamicSharedMemorySize, SM2);
        attr_done = 1;
    }

    int eb = (int)((E + 255) / 256);
    int gb = (NN + 127) / 128;
    int wb = (NN * 32 + 255) / 256;

    k_detect<<<1, 256>>>((const unsigned long long*)ei);
    k_zero_deg<<<NB, 256>>>();
    k_degcount<<<eb, 256>>>(ei, E);
    k_dinv<<<NB, 256>>>();
    k_scan1<<<NB, 256>>>();
    k_scan2<<<1, 512>>>();
    k_scan3<<<NB, 256>>>();
    k_scatter<<<eb, 256>>>(ei, E);

    // Layer 1: h1 = bf16(x @ W1); t1 = bf16(relu(agg(h1) + b1))
    k_gemm_tc<128, false><<<gb, 256, SM1>>>(x, W1, h1, NN);
    k_agg1<<<wb, 256>>>(h1, b1, t1);

    // Layer 2: h2 = bf16(t1 @ W2); out = mean(sigmoid(agg(h2) + b2))
    k_gemm_tc<64, true><<<gb, 256, SM2>>>(t1, W2, h2, NN);
    k_acc_zero<<<1, 64>>>();
    k_agg2<<<1480, 256>>>(h2, b2);
    k_final<<<1, 64>>>(out);
}

// round 5
// speedup vs baseline: 2.4748x; 1.0742x over previous
#include <cuda_runtime.h>
#include <cuda_bf16.h>
#include <cstdint>
#include <cstddef>

#define NN   100000
#define MAXE 1600000
#define NB   391          // ceil(NN/256)

// ---------------- device scratch ----------------
__device__ int   g_degi[NN];
__device__ float g_dinv[NN];
__device__ int   g_rowptr[NN + 1];
__device__ int   g_cursor[NN];
__device__ int   g_bsum[NB];
__device__ int   g_boff[NB];
__device__ int   g_csrc[MAXE];
__device__ __nv_bfloat16 g_h1[(size_t)NN * 128];  // dinv * (x @ W1)        (bf16)
__device__ __nv_bfloat16 g_t1[(size_t)NN * 128];  // relu(agg1 + b1)        (bf16)
__device__ __nv_bfloat16 g_h2[(size_t)NN * 64];   // dinv * (t1 @ W2)       (bf16)
__device__ float g_acc[64];
__device__ unsigned int g_done;

// ---------------- inline edge dtype detection (per block) -----------------
__device__ __forceinline__ int detect_e64(const void* eidx, int* sh) {
    if (threadIdx.x < 32) {
        unsigned long long v = ((const unsigned long long*)eidx)[threadIdx.x];
        unsigned m = __ballot_sync(0xffffffffu, (v >> 32) != 0ULL);
        if (threadIdx.x == 0) *sh = (m == 0u);
    }
    __syncthreads();
    return *sh;
}

// ---------------- degree count ----------------
__global__ void k_degcount(const void* __restrict__ eidx, long long E) {
    __shared__ int sh;
    int e64 = detect_e64(eidx, &sh);
    long long i = blockIdx.x * (long long)blockDim.x + threadIdx.x;
    if (i >= E) return;
    int d;
    if (e64) d = (int)((const long long*)eidx)[E + i];
    else     d = ((const int*)eidx)[E + i];
    atomicAdd(&g_degi[d], 1);
}

// ---------------- scan stage 1 (+ dinv) ----------------
__global__ void k_scan1() {
    __shared__ int sm[256];
    int i = blockIdx.x * 256 + threadIdx.x;
    int v = (i < NN) ? g_degi[i] : 0;
    if (i < NN) g_dinv[i] = rsqrtf((float)(v + 1));   // +1 self loop
    sm[threadIdx.x] = v;
    __syncthreads();
    for (int o = 128; o > 0; o >>= 1) {
        if (threadIdx.x < o) sm[threadIdx.x] += sm[threadIdx.x + o];
        __syncthreads();
    }
    if (threadIdx.x == 0) g_bsum[blockIdx.x] = sm[0];
}

// ---------------- scan stage 2 (+ zero acc/done) ----------------
__global__ void k_scan2() {
    __shared__ int sm[512];
    int v = (threadIdx.x < NB) ? g_bsum[threadIdx.x] : 0;
    sm[threadIdx.x] = v;
    __syncthreads();
    for (int o = 1; o < 512; o <<= 1) {
        int t = (threadIdx.x >= o) ? sm[threadIdx.x - o] : 0;
        __syncthreads();
        sm[threadIdx.x] += t;
        __syncthreads();
    }
    if (threadIdx.x < NB) g_boff[threadIdx.x] = sm[threadIdx.x] - v;  // exclusive
    if (threadIdx.x < 64) g_acc[threadIdx.x] = 0.f;
    if (threadIdx.x == 0) g_done = 0u;
}

// ---------------- scan stage 3 ----------------
__global__ void k_scan3() {
    __shared__ int sm[256];
    int i = blockIdx.x * 256 + threadIdx.x;
    int v = (i < NN) ? g_degi[i] : 0;
    sm[threadIdx.x] = v;
    __syncthreads();
    for (int o = 1; o < 256; o <<= 1) {
        int t = (threadIdx.x >= o) ? sm[threadIdx.x - o] : 0;
        __syncthreads();
        sm[threadIdx.x] += t;
        __syncthreads();
    }
    int excl = sm[threadIdx.x] - v + g_boff[blockIdx.x];
    if (i < NN) { g_rowptr[i] = excl; g_cursor[i] = excl; }
    if (i == NN - 1) g_rowptr[NN] = excl + v;
}

// ---------------- scatter: csrc only ----------------
__global__ void k_scatter(const void* __restrict__ eidx, long long E) {
    __shared__ int sh;
    int e64 = detect_e64(eidx, &sh);
    long long i = blockIdx.x * (long long)blockDim.x + threadIdx.x;
    if (i >= E) return;
    int s, d;
    if (e64) {
        const long long* p = (const long long*)eidx;
        s = (int)p[i];
        d = (int)p[E + i];
    } else {
        const int* p = (const int*)eidx;
        s = p[i];
        d = p[E + i];
    }
    int pos = atomicAdd(&g_cursor[d], 1);
    g_csrc[pos] = s;
}

// ---------------- tensor-core GEMM ----------------
__device__ __forceinline__ uint32_t smem_u32(const void* p) {
    return (uint32_t)__cvta_generic_to_shared(p);
}
__device__ __forceinline__ void ldsm4(uint32_t* r, uint32_t addr) {
    asm volatile("ldmatrix.sync.aligned.m8n8.x4.shared.b16 {%0,%1,%2,%3},[%4];"
                 : "=r"(r[0]), "=r"(r[1]), "=r"(r[2]), "=r"(r[3]) : "r"(addr));
}
__device__ __forceinline__ void ldsm4t(uint32_t* r, uint32_t addr) {
    asm volatile("ldmatrix.sync.aligned.m8n8.x4.trans.shared.b16 {%0,%1,%2,%3},[%4];"
                 : "=r"(r[0]), "=r"(r[1]), "=r"(r[2]), "=r"(r[3]) : "r"(addr));
}
__device__ __forceinline__ void mma16816(float* d, const uint32_t* a, const uint32_t* b) {
    asm volatile(
        "mma.sync.aligned.m16n8k16.row.col.f32.bf16.bf16.f32 "
        "{%0,%1,%2,%3},{%4,%5,%6,%7},{%8,%9},{%0,%1,%2,%3};"
        : "+f"(d[0]), "+f"(d[1]), "+f"(d[2]), "+f"(d[3])
        : "r"(a[0]), "r"(a[1]), "r"(a[2]), "r"(a[3]), "r"(b[0]), "r"(b[1]));
}

// C[nrows,BN](bf16) = rowscale[r] * (A[nrows,128] @ W[128,BN]).
template <int BN, bool A_BF16>
__global__ void __launch_bounds__(256)
k_gemm_tc(const void* __restrict__ Av, const float* __restrict__ W,
          const float* __restrict__ rowscale, __nv_bfloat16* __restrict__ C,
          int nrows) {
    const int LDA = 136;
    const int LDB = BN + 8;
    extern __shared__ __nv_bfloat16 smem[];
    __nv_bfloat16* As = smem;
    __nv_bfloat16* Bs = smem + 128 * LDA;

    int tid  = threadIdx.x;
    int lane = tid & 31;
    int w    = tid >> 5;
    int wm   = w & 3;
    int wn   = w >> 2;
    int row0 = blockIdx.x * 128;

    if (A_BF16) {
        const __nv_bfloat16* A = (const __nv_bfloat16*)Av;
        for (int idx = tid; idx < 128 * 16; idx += 256) {
            int r = idx >> 4, c8 = (idx & 15) * 8;
            uint4 v = make_uint4(0, 0, 0, 0);
            if (row0 + r < nrows)
                v = *(const uint4*)(A + (size_t)(row0 + r) * 128 + c8);
            *(uint4*)&As[r * LDA + c8] = v;
        }
    } else {
        const float* A = (const float*)Av;
        for (int idx = tid; idx < 128 * 32; idx += 256) {
            int r = idx >> 5, c4 = (idx & 31) * 4;
            float4 v = make_float4(0.f, 0.f, 0.f, 0.f);
            if (row0 + r < nrows)
                v = *(const float4*)(A + (size_t)(row0 + r) * 128 + c4);
            __nv_bfloat162 lo = __float22bfloat162_rn(make_float2(v.x, v.y));
            __nv_bfloat162 hi = __float22bfloat162_rn(make_float2(v.z, v.w));
            uint2 pk;
            pk.x = *(uint32_t*)&lo;
            pk.y = *(uint32_t*)&hi;
            *(uint2*)&As[r * LDA + c4] = pk;
        }
    }
    for (int idx = tid; idx < 128 * (BN / 4); idx += 256) {
        int r = idx / (BN / 4), c4 = (idx % (BN / 4)) * 4;
        float4 v = *(const float4*)(W + (size_t)r * BN + c4);
        __nv_bfloat162 lo = __float22bfloat162_rn(make_float2(v.x, v.y));
        __nv_bfloat162 hi = __float22bfloat162_rn(make_float2(v.z, v.w));
        uint2 pk;
        pk.x = *(uint32_t*)&lo;
        pk.y = *(uint32_t*)&hi;
        *(uint2*)&Bs[r * LDB + c4] = pk;
    }
    __syncthreads();

    const int NF8 = BN / 16;
    const int NT  = NF8 / 2;
    float acc[2][NF8][4];
#pragma unroll
    for (int i = 0; i < 2; i++)
#pragma unroll
        for (int j = 0; j < NF8; j++)
#pragma unroll
            for (int q = 0; q < 4; q++) acc[i][j][q] = 0.f;

    int rsel = lane & 15;
    int csel = (lane >> 4) * 8;
    int mw0  = wm * 32;
    int nw0  = wn * (BN / 2);

#pragma unroll
    for (int ks = 0; ks < 8; ks++) {
        int k0 = ks * 16;
        uint32_t af[2][4];
#pragma unroll
        for (int mi = 0; mi < 2; mi++)
            ldsm4(af[mi], smem_u32(&As[(mw0 + mi * 16 + rsel) * LDA + k0 + csel]));
        uint32_t bf[NT][4];
#pragma unroll
        for (int nt = 0; nt < NT; nt++)
            ldsm4t(bf[nt], smem_u32(&Bs[(k0 + rsel) * LDB + nw0 + nt * 16 + csel]));
#pragma unroll
        for (int mi = 0; mi < 2; mi++)
#pragma unroll
            for (int nj = 0; nj < NF8; nj++)
                mma16816(acc[mi][nj], af[mi], &bf[nj >> 1][(nj & 1) * 2]);
    }

    int g = lane >> 2, q = lane & 3;
#pragma unroll
    for (int mi = 0; mi < 2; mi++) {
        int r0 = row0 + mw0 + mi * 16 + g;
        float sc0 = (r0 < nrows)     ? rowscale[r0]     : 0.f;
        float sc1 = (r0 + 8 < nrows) ? rowscale[r0 + 8] : 0.f;
#pragma unroll
        for (int nj = 0; nj < NF8; nj++) {
            int col = nw0 + nj * 8 + q * 2;
            if (r0 < nrows) {
                __nv_bfloat162 v = __float22bfloat162_rn(
                    make_float2(acc[mi][nj][0] * sc0, acc[mi][nj][1] * sc0));
                *(__nv_bfloat162*)(C + (size_t)r0 * BN + col) = v;
            }
            if (r0 + 8 < nrows) {
                __nv_bfloat162 v = __float22bfloat162_rn(
                    make_float2(acc[mi][nj][2] * sc1, acc[mi][nj][3] * sc1));
                *(__nv_bfloat162*)(C + (size_t)(r0 + 8) * BN + col) = v;
            }
        }
    }
}

// ---------------- CSR gather-sum (pure adds, h is pre-scaled by dinv) -----
__device__ __forceinline__ void ldrow8(const __nv_bfloat16* p, float* f) {
    uint2 u = *(const uint2*)p;
    float2 a = __bfloat1622float2(*(__nv_bfloat162*)&u.x);
    float2 b = __bfloat1622float2(*(__nv_bfloat162*)&u.y);
    f[0] = a.x; f[1] = a.y; f[2] = b.x; f[3] = b.y;
}

template <int F>
__device__ __forceinline__ void csr_gather(const __nv_bfloat16* hl, int node,
                                           float* acc) {
    ldrow8(hl + (size_t)node * F, acc);   // self row (pre-scaled)
    int beg = g_rowptr[node], end = g_rowptr[node + 1];
    int j = beg;
    for (; j + 4 <= end; j += 4) {
        int s0 = g_csrc[j],     s1 = g_csrc[j + 1];
        int s2 = g_csrc[j + 2], s3 = g_csrc[j + 3];
        float f0[4], f1[4], f2[4], f3[4];
        ldrow8(hl + (size_t)s0 * F, f0);
        ldrow8(hl + (size_t)s1 * F, f1);
        ldrow8(hl + (size_t)s2 * F, f2);
        ldrow8(hl + (size_t)s3 * F, f3);
#pragma unroll
        for (int c = 0; c < 4; c++)
            acc[c] += (f0[c] + f1[c]) + (f2[c] + f3[c]);
    }
    for (; j < end; j++) {
        int s = g_csrc[j];
        float f[4];
        ldrow8(hl + (size_t)s * F, f);
#pragma unroll
        for (int c = 0; c < 4; c++) acc[c] += f[c];
    }
}

// agg layer 1: t1[node,:] = bf16(relu(dinv[node]*gathersum + b1))
__global__ void __launch_bounds__(256)
k_agg1(const __nv_bfloat16* __restrict__ h, const float* __restrict__ b1,
       __nv_bfloat16* __restrict__ t1) {
    int node = (blockIdx.x * 256 + threadIdx.x) >> 5;
    int lane = threadIdx.x & 31;
    if (node >= NN) return;
    float acc[4];
    csr_gather<128>(h + lane * 4, node, acc);
    float dn = g_dinv[node];
    float4 bb = *(const float4*)(b1 + lane * 4);
    float2 lo = make_float2(fmaxf(dn * acc[0] + bb.x, 0.f),
                            fmaxf(dn * acc[1] + bb.y, 0.f));
    float2 hi = make_float2(fmaxf(dn * acc[2] + bb.z, 0.f),
                            fmaxf(dn * acc[3] + bb.w, 0.f));
    uint2 pk;
    __nv_bfloat162 l2 = __float22bfloat162_rn(lo);
    __nv_bfloat162 h2 = __float22bfloat162_rn(hi);
    pk.x = *(uint32_t*)&l2;
    pk.y = *(uint32_t*)&h2;
    *(uint2*)(t1 + (size_t)node * 128 + lane * 4) = pk;
}

// agg layer 2 (2 nodes per warp) fused with sigmoid + mean + final output
__global__ void __launch_bounds__(256)
k_agg2(const __nv_bfloat16* __restrict__ h, const float* __restrict__ b2,
       float* __restrict__ out) {
    __shared__ float sm[64];
    if (threadIdx.x < 64) sm[threadIdx.x] = 0.f;
    __syncthreads();

    int lane = threadIdx.x & 31;
    int half = lane >> 4;
    int l16  = lane & 15;
    int wg   = (blockIdx.x * 256 + threadIdx.x) >> 5;
    int stride = gridDim.x * 8 * 2;

    float4 bb = *(const float4*)(b2 + l16 * 4);
    float s[4] = {0.f, 0.f, 0.f, 0.f};

    for (int node = wg * 2 + half; node < NN; node += stride) {
        float acc[4];
        csr_gather<64>(h + l16 * 4, node, acc);
        float dn = g_dinv[node];
        s[0] += 1.0f / (1.0f + __expf(-(dn * acc[0] + bb.x)));
        s[1] += 1.0f / (1.0f + __expf(-(dn * acc[1] + bb.y)));
        s[2] += 1.0f / (1.0f + __expf(-(dn * acc[2] + bb.z)));
        s[3] += 1.0f / (1.0f + __expf(-(dn * acc[3] + bb.w)));
    }
#pragma unroll
    for (int c = 0; c < 4; c++) atomicAdd(&sm[l16 * 4 + c], s[c]);
    __syncthreads();
    if (threadIdx.x < 64) atomicAdd(&g_acc[threadIdx.x], sm[threadIdx.x]);
    __threadfence();
    __syncthreads();

    __shared__ unsigned s_last;
    if (threadIdx.x == 0)
        s_last = (atomicAdd(&g_done, 1u) == (unsigned)(gridDim.x - 1));
    __syncthreads();
    if (s_last) {
        __threadfence();
        if (threadIdx.x < 64) {
            float v = atomicAdd(&g_acc[threadIdx.x], 0.f);
            out[threadIdx.x] = v * (1.0f / NN);
        }
    }
}

// ---------------- launch ----------------
extern "C" void kernel_launch(void* const* d_in, const int* in_sizes, int n_in,
                              void* d_out, int out_size) {
    const float* x  = (const float*)d_in[0];
    const void*  ei = d_in[1];
    const float* W1 = (const float*)d_in[2];
    const float* b1 = (const float*)d_in[3];
    const float* W2 = (const float*)d_in[4];
    const float* b2 = (const float*)d_in[5];
    float* out = (float*)d_out;
    long long E = in_sizes[1] / 2;

    __nv_bfloat16 *h1, *t1, *h2;
    float *dinv;
    int *degi;
    cudaGetSymbolAddress((void**)&h1, g_h1);
    cudaGetSymbolAddress((void**)&t1, g_t1);
    cudaGetSymbolAddress((void**)&h2, g_h2);
    cudaGetSymbolAddress((void**)&dinv, g_dinv);
    cudaGetSymbolAddress((void**)&degi, g_degi);

    const int SM1 = (128 * 136 + 128 * 136) * 2;  // 69632 B
    const int SM2 = (128 * 136 + 128 * 72) * 2;   // 53248 B

    static cudaStream_t s2 = nullptr;
    static cudaEvent_t ev0 = nullptr, ev1 = nullptr;
    if (!s2) {
        cudaFuncSetAttribute(k_gemm_tc<128, false>,
                             cudaFuncAttributeMaxDynamicSharedMemorySize, SM1);
        cudaFuncSetAttribute(k_gemm_tc<64, true>,
                             cudaFuncAttributeMaxDynamicSharedMemorySize, SM2);
        cudaStreamCreateWithFlags(&s2, cudaStreamNonBlocking);
        cudaEventCreateWithFlags(&ev0, cudaEventDisableTiming);
        cudaEventCreateWithFlags(&ev1, cudaEventDisableTiming);
    }

    int eb = (int)((E + 255) / 256);
    int gb = (NN + 127) / 128;
    int wb = (NN * 32 + 255) / 256;

    // ---- fork: GEMM1 on side stream ----
    cudaEventRecord(ev0, 0);
    cudaStreamWaitEvent(s2, ev0, 0);

    cudaMemsetAsync(degi, 0, NN * sizeof(int), 0);
    k_degcount<<<eb, 256>>>(ei, E);
    k_scan1<<<NB, 256>>>();

    cudaEventRecord(ev1, 0);
    cudaStreamWaitEvent(s2, ev1, 0);
    k_gemm_tc<128, false><<<gb, 256, SM1, s2>>>(x, W1, dinv, h1, NN);
    cudaEventRecord(ev0, s2);

    k_scan2<<<1, 512>>>();
    k_scan3<<<NB, 256>>>();
    k_scatter<<<eb, 256>>>(ei, E);

    // join: agg1 needs CSR (stream 0) + h1 (stream s2)
    cudaStreamWaitEvent(0, ev0, 0);
    k_agg1<<<wb, 256>>>(h1, b1, t1);

    // Layer 2
    k_gemm_tc<64, true><<<gb, 256, SM2>>>(t1, W2, dinv, h2, NN);
    k_agg2<<<1024, 256>>>(h2, b2, out);
}